// round 11
// baseline (speedup 1.0000x reference)
#include <cuda_runtime.h>

// Problem shape (fixed by reference setup_inputs)
#define BB 32
#define NN 8
#define LQ 256
#define LD 512
#define DD 768
#define D4 (DD / 4)                      // 192 float4 per feature row
#define LSPLIT 8                          // question L-dim split
#define LCH (LQ / LSPLIT)                 // 32 q-rows per q-block
#define QBLK (BB * LSPLIT)                // 256 question blocks
#define BPS 2                             // doc blocks per (b,n) slice
#define NBLK2 (BB * NN * BPS)             // 512 doc blocks
#define TT D4                             // 192 threads: one float4 column each
#define ROWS (LD / BPS)                   // 256 doc rows per doc block
#define F4_PER_SLICE (LD * D4)            // 98304 float4 per (b,n)

// Scratch (allocation-free rule: __device__ globals; zero-initialized at load)
__device__ float4       g_qpart[QBLK * D4];
__device__ double       g_acc;
__device__ unsigned int g_count;   // doc-block completion counter
__device__ unsigned int g_qcount;  // question-block completion counter

// ---------------------------------------------------------------------------
// Single fused kernel (champion R7 structure, BPS=2 overhead trim).
//  blocks [0, QBLK):       question partial sums -> g_qpart, bump g_qcount.
//  blocks [QBLK, +NBLK2):  stream a 256-row doc chunk (column sums, weight-
//                          free), wait for q partials (already done), dot
//                          with qsum, reduce, atomic into g_acc.
//  Last doc block writes out and resets scratch (graph-replay safe).
__global__ void __launch_bounds__(TT) fused(const float4* __restrict__ q,
                                            const float*  __restrict__ docs,
                                            const int*    __restrict__ is_ans,
                                            float*        __restrict__ out) {
    const int t = threadIdx.x;            // 0..191 = float4 column

    // ---------------- question blocks (exit early) ----------------
    if (blockIdx.x < QBLK) {
        const int b = blockIdx.x / LSPLIT;
        const int c = blockIdx.x % LSPLIT;
        const float4* base = q + ((size_t)b * LQ + (size_t)c * LCH) * D4 + t;
        float4 s = make_float4(0.f, 0.f, 0.f, 0.f);
#pragma unroll 8
        for (int l = 0; l < LCH; ++l) {
            const float4 v = base[(size_t)l * D4];
            s.x += v.x; s.y += v.y; s.z += v.z; s.w += v.w;
        }
        g_qpart[(size_t)blockIdx.x * D4 + t] = s;
        __threadfence();
        __syncthreads();
        if (t == 0) atomicAdd(&g_qcount, 1u);
        return;
    }

    // ---------------- doc blocks ----------------
    __shared__ double warp_sums[TT / 32];

    const int db    = blockIdx.x - QBLK;  // 0..511
    const int slice = db / BPS;           // 0..255  (= b*NN + n)
    const int part  = db % BPS;
    const int b     = slice / NN;

    const float4* base = (const float4*)docs +
                         (size_t)slice * F4_PER_SLICE +
                         (size_t)part * ROWS * D4 + t;

    // Column sum over ROWS rows: pure streaming (evict-first loads).
    float4 cs = make_float4(0.f, 0.f, 0.f, 0.f);
#pragma unroll 8
    for (int l = 0; l < ROWS; ++l) {
        const float4 v = __ldcs(base + (size_t)l * D4);
        cs.x += v.x; cs.y += v.y; cs.z += v.z; cs.w += v.w;
    }

    // Wait for question partials (normally already complete — no real spin).
    if (t == 0) {
        while (atomicAdd(&g_qcount, 0u) < QBLK) { }
    }
    __syncthreads();
    __threadfence();  // acquire: make g_qpart writes visible to all threads

    // Gather this column's q-weight (sum of the 8 partials) and dot.
    float4 w = make_float4(0.f, 0.f, 0.f, 0.f);
#pragma unroll
    for (int c = 0; c < LSPLIT; ++c) {
        const float4 v = g_qpart[(size_t)(b * LSPLIT + c) * D4 + t];
        w.x += v.x; w.y += v.y; w.z += v.z; w.w += v.w;
    }
    float acc = cs.x * w.x + cs.y * w.y + cs.z * w.z + cs.w * w.w;
    acc *= (is_ans[slice] != 0) ? -1.f : 1.f;

    // Warp reduce (fp32), then cross-warp in double.
#pragma unroll
    for (int off = 16; off > 0; off >>= 1)
        acc += __shfl_down_sync(0xFFFFFFFFu, acc, off);

    const int warp = t >> 5;
    if ((t & 31) == 0) warp_sums[warp] = (double)acc;
    __syncthreads();

    if (t == 0) {
        double s = 0.0;
#pragma unroll
        for (int w2 = 0; w2 < TT / 32; ++w2) s += warp_sums[w2];
        atomicAdd(&g_acc, s);
        __threadfence();
        const unsigned int done = atomicAdd(&g_count, 1u);
        if (done == NBLK2 - 1) {
            const double tot = *((volatile double*)&g_acc);
            out[0] = (float)(tot * (1.0 / ((double)LQ * (double)LD)));
            // Reset scratch for the next graph replay.
            g_acc    = 0.0;
            g_qcount = 0u;
            __threadfence();
            g_count  = 0u;
        }
    }
}

// ---------------------------------------------------------------------------
extern "C" void kernel_launch(void* const* d_in, const int* in_sizes, int n_in,
                              void* d_out, int out_size) {
    const float* questions = (const float*)d_in[0];
    const float* docs      = (const float*)d_in[1];
    const int*   is_ans    = (const int*)d_in[2];
    float*       out       = (float*)d_out;

    fused<<<QBLK + NBLK2, TT>>>((const float4*)questions, docs, is_ans, out);
}

// round 12
// speedup vs baseline: 1.0309x; 1.0309x over previous
#include <cuda_runtime.h>

// Problem shape (fixed by reference setup_inputs)
#define BB 32
#define NN 8
#define LQ 256
#define LD 512
#define DD 768
#define D4 (DD / 4)                      // 192 float4 per feature row
#define LSPLIT 8                          // question L-dim split
#define LCH (LQ / LSPLIT)                 // 32 q-rows per q-block
#define QBLK (BB * LSPLIT)                // 256 question blocks
#define BPS 4                             // doc blocks per (b,n) slice
#define NBLK2 (BB * NN * BPS)             // 1024 doc blocks
#define TT D4                             // 192 threads: one float4 column each
#define ROWS (LD / BPS)                   // 128 doc rows per doc block
#define F4_PER_SLICE (LD * D4)            // 98304 float4 per (b,n)

// Scratch (allocation-free rule: __device__ globals; zero-initialized at load)
__device__ float4       g_qpart[QBLK * D4];
__device__ double       g_acc;
__device__ unsigned int g_count;   // doc-block completion counter
__device__ unsigned int g_qcount;  // question-block completion counter

// ---------------------------------------------------------------------------
// Single fused kernel (champion R7 configuration).
//  blocks [0, QBLK):       question partial sums -> g_qpart, bump g_qcount.
//  blocks [QBLK, +NBLK2):  stream a 128-row doc chunk (column sums, weight-
//                          free), wait for q partials (already done), dot
//                          with qsum, reduce, atomic into g_acc.
//  Last doc block writes out and resets scratch (graph-replay safe).
__global__ void __launch_bounds__(TT) fused(const float4* __restrict__ q,
                                            const float*  __restrict__ docs,
                                            const int*    __restrict__ is_ans,
                                            float*        __restrict__ out) {
    const int t = threadIdx.x;            // 0..191 = float4 column

    // ---------------- question blocks (exit early) ----------------
    if (blockIdx.x < QBLK) {
        const int b = blockIdx.x / LSPLIT;
        const int c = blockIdx.x % LSPLIT;
        const float4* base = q + ((size_t)b * LQ + (size_t)c * LCH) * D4 + t;
        float4 s = make_float4(0.f, 0.f, 0.f, 0.f);
#pragma unroll 8
        for (int l = 0; l < LCH; ++l) {
            const float4 v = base[(size_t)l * D4];
            s.x += v.x; s.y += v.y; s.z += v.z; s.w += v.w;
        }
        g_qpart[(size_t)blockIdx.x * D4 + t] = s;
        __threadfence();
        __syncthreads();
        if (t == 0) atomicAdd(&g_qcount, 1u);
        return;
    }

    // ---------------- doc blocks ----------------
    __shared__ double warp_sums[TT / 32];

    const int db    = blockIdx.x - QBLK;  // 0..1023
    const int slice = db / BPS;           // 0..255  (= b*NN + n)
    const int part  = db % BPS;
    const int b     = slice / NN;

    // Hoist the sign load off the epilogue critical path.
    const float sign = (__ldg(is_ans + slice) != 0) ? -1.f : 1.f;

    const float4* base = (const float4*)docs +
                         (size_t)slice * F4_PER_SLICE +
                         (size_t)part * ROWS * D4 + t;

    // Column sum over ROWS rows: pure streaming (evict-first loads).
    float4 cs = make_float4(0.f, 0.f, 0.f, 0.f);
#pragma unroll 8
    for (int l = 0; l < ROWS; ++l) {
        const float4 v = __ldcs(base + (size_t)l * D4);
        cs.x += v.x; cs.y += v.y; cs.z += v.z; cs.w += v.w;
    }

    // Wait for question partials (normally already complete — no real spin).
    if (t == 0) {
        while (atomicAdd(&g_qcount, 0u) < QBLK) { }
    }
    __syncthreads();
    __threadfence();  // acquire: make g_qpart writes visible to all threads

    // Gather this column's q-weight (sum of the 8 partials) and dot.
    float4 w = make_float4(0.f, 0.f, 0.f, 0.f);
#pragma unroll
    for (int c = 0; c < LSPLIT; ++c) {
        const float4 v = g_qpart[(size_t)(b * LSPLIT + c) * D4 + t];
        w.x += v.x; w.y += v.y; w.z += v.z; w.w += v.w;
    }
    float acc = (cs.x * w.x + cs.y * w.y + cs.z * w.z + cs.w * w.w) * sign;

    // Warp reduce (fp32), then cross-warp in double.
#pragma unroll
    for (int off = 16; off > 0; off >>= 1)
        acc += __shfl_down_sync(0xFFFFFFFFu, acc, off);

    const int warp = t >> 5;
    if ((t & 31) == 0) warp_sums[warp] = (double)acc;
    __syncthreads();

    if (t == 0) {
        double s = 0.0;
#pragma unroll
        for (int w2 = 0; w2 < TT / 32; ++w2) s += warp_sums[w2];
        atomicAdd(&g_acc, s);
        __threadfence();
        const unsigned int done = atomicAdd(&g_count, 1u);
        if (done == NBLK2 - 1) {
            const double tot = *((volatile double*)&g_acc);
            out[0] = (float)(tot * (1.0 / ((double)LQ * (double)LD)));
            // Reset scratch for the next graph replay.
            g_acc    = 0.0;
            g_qcount = 0u;
            __threadfence();
            g_count  = 0u;
        }
    }
}

// ---------------------------------------------------------------------------
extern "C" void kernel_launch(void* const* d_in, const int* in_sizes, int n_in,
                              void* d_out, int out_size) {
    const float* questions = (const float*)d_in[0];
    const float* docs      = (const float*)d_in[1];
    const int*   is_ans    = (const int*)d_in[2];
    float*       out       = (float*)d_out;

    fused<<<QBLK + NBLK2, TT>>>((const float4*)questions, docs, is_ans, out);
}

// round 13
// speedup vs baseline: 1.0501x; 1.0187x over previous
#include <cuda_runtime.h>

// Problem shape (fixed by reference setup_inputs)
#define BB 32
#define NN 8
#define LQ 256
#define LD 512
#define DD 768
#define D4 (DD / 4)                      // 192 float4 per feature row
#define LSPLIT 8                          // question L-dim split
#define LCH (LQ / LSPLIT)                 // 32 q-rows per q-block
#define QBLK (BB * LSPLIT)                // 256 question blocks
#define BPS 4                             // doc blocks per (b,n) slice
#define NBLK2 (BB * NN * BPS)             // 1024 doc blocks
#define TT D4                             // 192 threads: one float4 column each
#define ROWS (LD / BPS)                   // 128 doc rows per doc block
#define F4_PER_SLICE (LD * D4)            // 98304 float4 per (b,n)

// Scratch (allocation-free rule: __device__ globals; zero-initialized at load)
__device__ float4       g_qpart[QBLK * D4];
__device__ double       g_acc;
__device__ unsigned int g_count;   // doc-block completion counter
__device__ unsigned int g_qcount;  // question-block completion counter

// ---------------------------------------------------------------------------
// Single fused kernel (champion configuration, R7).
//  blocks [0, QBLK):       question partial sums -> g_qpart, bump g_qcount.
//  blocks [QBLK, +NBLK2):  stream a 128-row doc chunk (column sums, weight-
//                          free), wait for q partials (already done), dot
//                          with qsum, reduce, atomic into g_acc.
//  Last doc block writes out and resets scratch (graph-replay safe).
__global__ void __launch_bounds__(TT) fused(const float4* __restrict__ q,
                                            const float*  __restrict__ docs,
                                            const int*    __restrict__ is_ans,
                                            float*        __restrict__ out) {
    const int t = threadIdx.x;            // 0..191 = float4 column

    // ---------------- question blocks (exit early) ----------------
    if (blockIdx.x < QBLK) {
        const int b = blockIdx.x / LSPLIT;
        const int c = blockIdx.x % LSPLIT;
        const float4* base = q + ((size_t)b * LQ + (size_t)c * LCH) * D4 + t;
        float4 s = make_float4(0.f, 0.f, 0.f, 0.f);
#pragma unroll 8
        for (int l = 0; l < LCH; ++l) {
            const float4 v = base[(size_t)l * D4];
            s.x += v.x; s.y += v.y; s.z += v.z; s.w += v.w;
        }
        g_qpart[(size_t)blockIdx.x * D4 + t] = s;
        __threadfence();
        __syncthreads();
        if (t == 0) atomicAdd(&g_qcount, 1u);
        return;
    }

    // ---------------- doc blocks ----------------
    __shared__ double warp_sums[TT / 32];

    const int db    = blockIdx.x - QBLK;  // 0..1023
    const int slice = db / BPS;           // 0..255  (= b*NN + n)
    const int part  = db % BPS;
    const int b     = slice / NN;

    const float4* base = (const float4*)docs +
                         (size_t)slice * F4_PER_SLICE +
                         (size_t)part * ROWS * D4 + t;

    // Column sum over ROWS rows: pure streaming (evict-first loads).
    float4 cs = make_float4(0.f, 0.f, 0.f, 0.f);
#pragma unroll 8
    for (int l = 0; l < ROWS; ++l) {
        const float4 v = __ldcs(base + (size_t)l * D4);
        cs.x += v.x; cs.y += v.y; cs.z += v.z; cs.w += v.w;
    }

    // Wait for question partials (normally already complete — no real spin).
    if (t == 0) {
        while (atomicAdd(&g_qcount, 0u) < QBLK) { }
    }
    __syncthreads();
    __threadfence();  // acquire: make g_qpart writes visible to all threads

    // Gather this column's q-weight (sum of the 8 partials) and dot.
    float4 w = make_float4(0.f, 0.f, 0.f, 0.f);
#pragma unroll
    for (int c = 0; c < LSPLIT; ++c) {
        const float4 v = g_qpart[(size_t)(b * LSPLIT + c) * D4 + t];
        w.x += v.x; w.y += v.y; w.z += v.z; w.w += v.w;
    }
    float acc = cs.x * w.x + cs.y * w.y + cs.z * w.z + cs.w * w.w;
    acc *= (is_ans[slice] != 0) ? -1.f : 1.f;

    // Warp reduce (fp32), then cross-warp in double.
#pragma unroll
    for (int off = 16; off > 0; off >>= 1)
        acc += __shfl_down_sync(0xFFFFFFFFu, acc, off);

    const int warp = t >> 5;
    if ((t & 31) == 0) warp_sums[warp] = (double)acc;
    __syncthreads();

    if (t == 0) {
        double s = 0.0;
#pragma unroll
        for (int w2 = 0; w2 < TT / 32; ++w2) s += warp_sums[w2];
        atomicAdd(&g_acc, s);
        __threadfence();
        const unsigned int done = atomicAdd(&g_count, 1u);
        if (done == NBLK2 - 1) {
            const double tot = *((volatile double*)&g_acc);
            out[0] = (float)(tot * (1.0 / ((double)LQ * (double)LD)));
            // Reset scratch for the next graph replay.
            g_acc    = 0.0;
            g_qcount = 0u;
            __threadfence();
            g_count  = 0u;
        }
    }
}

// ---------------------------------------------------------------------------
extern "C" void kernel_launch(void* const* d_in, const int* in_sizes, int n_in,
                              void* d_out, int out_size) {
    const float* questions = (const float*)d_in[0];
    const float* docs      = (const float*)d_in[1];
    const int*   is_ans    = (const int*)d_in[2];
    float*       out       = (float*)d_out;

    fused<<<QBLK + NBLK2, TT>>>((const float4*)questions, docs, is_ans, out);
}

// round 14
// speedup vs baseline: 1.0680x; 1.0170x over previous
#include <cuda_runtime.h>

// Problem shape (fixed by reference setup_inputs)
#define BB 32
#define NN 8
#define LQ 256
#define LD 512
#define DD 768
#define D4 (DD / 4)                      // 192 float4 per feature row
#define LSPLIT 8                          // question L-dim split
#define LCH (LQ / LSPLIT)                 // 32 q-rows per q-block
#define QBLK (BB * LSPLIT)                // 256 question blocks
#define BPS 4                             // doc blocks per (b,n) slice
#define NBLK2 (BB * NN * BPS)             // 1024 doc blocks
#define TT D4                             // 192 threads: one float4 column each
#define ROWS (LD / BPS)                   // 128 doc rows per doc block
#define F4_PER_SLICE (LD * D4)            // 98304 float4 per (b,n)

// Scratch (allocation-free rule: __device__ globals; zero-initialized at load)
__device__ float4       g_qpart[QBLK * D4];
__device__ double       g_acc;
__device__ unsigned int g_count;   // doc-block completion counter
__device__ unsigned int g_qcount;  // question-block completion counter

// ---------------------------------------------------------------------------
// Single fused kernel (champion configuration, R7 — FINAL).
//  blocks [0, QBLK):       question partial sums -> g_qpart, bump g_qcount.
//  blocks [QBLK, +NBLK2):  stream a 128-row doc chunk (column sums, weight-
//                          free), wait for q partials (already done), dot
//                          with qsum, reduce, atomic into g_acc.
//  Last doc block writes out and resets scratch (graph-replay safe).
__global__ void __launch_bounds__(TT) fused(const float4* __restrict__ q,
                                            const float*  __restrict__ docs,
                                            const int*    __restrict__ is_ans,
                                            float*        __restrict__ out) {
    const int t = threadIdx.x;            // 0..191 = float4 column

    // ---------------- question blocks (exit early) ----------------
    if (blockIdx.x < QBLK) {
        const int b = blockIdx.x / LSPLIT;
        const int c = blockIdx.x % LSPLIT;
        const float4* base = q + ((size_t)b * LQ + (size_t)c * LCH) * D4 + t;
        float4 s = make_float4(0.f, 0.f, 0.f, 0.f);
#pragma unroll 8
        for (int l = 0; l < LCH; ++l) {
            const float4 v = base[(size_t)l * D4];
            s.x += v.x; s.y += v.y; s.z += v.z; s.w += v.w;
        }
        g_qpart[(size_t)blockIdx.x * D4 + t] = s;
        __threadfence();
        __syncthreads();
        if (t == 0) atomicAdd(&g_qcount, 1u);
        return;
    }

    // ---------------- doc blocks ----------------
    __shared__ double warp_sums[TT / 32];

    const int db    = blockIdx.x - QBLK;  // 0..1023
    const int slice = db / BPS;           // 0..255  (= b*NN + n)
    const int part  = db % BPS;
    const int b     = slice / NN;

    const float4* base = (const float4*)docs +
                         (size_t)slice * F4_PER_SLICE +
                         (size_t)part * ROWS * D4 + t;

    // Column sum over ROWS rows: pure streaming (evict-first loads).
    float4 cs = make_float4(0.f, 0.f, 0.f, 0.f);
#pragma unroll 8
    for (int l = 0; l < ROWS; ++l) {
        const float4 v = __ldcs(base + (size_t)l * D4);
        cs.x += v.x; cs.y += v.y; cs.z += v.z; cs.w += v.w;
    }

    // Wait for question partials (normally already complete — no real spin).
    if (t == 0) {
        while (atomicAdd(&g_qcount, 0u) < QBLK) { }
    }
    __syncthreads();
    __threadfence();  // acquire: make g_qpart writes visible to all threads

    // Gather this column's q-weight (sum of the 8 partials) and dot.
    float4 w = make_float4(0.f, 0.f, 0.f, 0.f);
#pragma unroll
    for (int c = 0; c < LSPLIT; ++c) {
        const float4 v = g_qpart[(size_t)(b * LSPLIT + c) * D4 + t];
        w.x += v.x; w.y += v.y; w.z += v.z; w.w += v.w;
    }
    float acc = cs.x * w.x + cs.y * w.y + cs.z * w.z + cs.w * w.w;
    acc *= (is_ans[slice] != 0) ? -1.f : 1.f;

    // Warp reduce (fp32), then cross-warp in double.
#pragma unroll
    for (int off = 16; off > 0; off >>= 1)
        acc += __shfl_down_sync(0xFFFFFFFFu, acc, off);

    const int warp = t >> 5;
    if ((t & 31) == 0) warp_sums[warp] = (double)acc;
    __syncthreads();

    if (t == 0) {
        double s = 0.0;
#pragma unroll
        for (int w2 = 0; w2 < TT / 32; ++w2) s += warp_sums[w2];
        atomicAdd(&g_acc, s);
        __threadfence();
        const unsigned int done = atomicAdd(&g_count, 1u);
        if (done == NBLK2 - 1) {
            const double tot = *((volatile double*)&g_acc);
            out[0] = (float)(tot * (1.0 / ((double)LQ * (double)LD)));
            // Reset scratch for the next graph replay.
            g_acc    = 0.0;
            g_qcount = 0u;
            __threadfence();
            g_count  = 0u;
        }
    }
}

// ---------------------------------------------------------------------------
extern "C" void kernel_launch(void* const* d_in, const int* in_sizes, int n_in,
                              void* d_out, int out_size) {
    const float* questions = (const float*)d_in[0];
    const float* docs      = (const float*)d_in[1];
    const int*   is_ans    = (const int*)d_in[2];
    float*       out       = (float*)d_out;

    fused<<<QBLK + NBLK2, TT>>>((const float4*)questions, docs, is_ans, out);
}